// round 6
// baseline (speedup 1.0000x reference)
#include <cuda_runtime.h>
#include <cuda_fp16.h>
#include <cstdint>

#define NTOK 49
#define NH   12
#define NWIN 64
#define NBLK 8192
#define NROWS (NBLK * NTOK)    /* 401408 = 3136*128 */
#define NMT  3136
#define SCALE 0.17677669529663687f

/* gemm smem (u32 units): A [128 rows][196], B [128 cols][20] */
#define GA_STRIDE 196
#define GB_OFF    25088
#define GSMEM_U32 27648
#define GSMEM_BYTES (GSMEM_U32 * 4)   /* 110592 */

/* attn smem (u32 units): 2 qkv buffers, P, S */
#define ABUF 3252
#define AQ_OFF  0
#define AK_OFF  980
#define AVT_OFF 2100
#define AP_OFF  6504
#define AS_OFF  8808
#define ASMEM_U32 12648
#define ASMEM_BYTES (ASMEM_U32 * 4)   /* 50592 */

/* ---------------- device scratch ---------------- */
__device__ uint32_t g_wq[9 * 12 * 128 * 16];    /* qkv_w fp16 packed  */
__device__ uint32_t g_wp[3 * 12 * 128 * 16];    /* proj_w fp16 packed */
__device__ uint32_t g_q [(size_t)NBLK * NH * 980];
__device__ uint32_t g_k [(size_t)NBLK * NH * 980];
__device__ uint32_t g_vt[(size_t)NBLK * NH * 1152];
__device__ uint32_t g_ob[(size_t)NROWS * 196];
__device__ float    g_bm[NWIN * NH * NTOK * NTOK];

/* ---------------- helpers ---------------- */
__device__ __forceinline__ int SLOT(int p7) { return ((p7 & 3) << 1) | (p7 >> 2); }

__device__ __forceinline__ uint32_t smem_u32(const void* p) {
    uint32_t a;
    asm("{ .reg .u64 t; cvta.to.shared.u64 t, %1; cvt.u32.u64 %0, t; }" : "=r"(a) : "l"(p));
    return a;
}
__device__ __forceinline__ uint32_t h2u(float a, float b) {
    __half2 h = __floats2half2_rn(a, b);
    return *reinterpret_cast<uint32_t*>(&h);
}
__device__ __forceinline__ void cpa16(uint32_t dst, const void* src) {
    asm volatile("cp.async.ca.shared.global [%0], [%1], 16;"
                 :: "r"(dst), "l"(__cvta_generic_to_global(src)));
}
#define CP_COMMIT() asm volatile("cp.async.commit_group;" ::: "memory")
#define CP_WAIT(n)  asm volatile("cp.async.wait_group %0;" :: "n"(n) : "memory")

__device__ __forceinline__ void mma16(float* c, uint32_t a0, uint32_t a1, uint32_t a2,
                                      uint32_t a3, uint32_t b0, uint32_t b1) {
    asm volatile(
        "mma.sync.aligned.m16n8k16.row.col.f32.f16.f16.f32 "
        "{%0,%1,%2,%3},{%4,%5,%6,%7},{%8,%9},{%0,%1,%2,%3};"
        : "+f"(c[0]), "+f"(c[1]), "+f"(c[2]), "+f"(c[3])
        : "r"(a0), "r"(a1), "r"(a2), "r"(a3), "r"(b0), "r"(b1));
}

/* ---------------- prep: pack weights fp16 fragment layout ---------------- */
__global__ void prep_pack(const float* __restrict__ qkv_w, const float* __restrict__ proj_w) {
    int i = blockIdx.x * 256 + threadIdx.x;
    const float* src;
    __half* dst;
    if (i < 1152 * 384) { src = qkv_w; dst = (__half*)g_wq; }
    else { i -= 1152 * 384; src = proj_w; dst = (__half*)g_wp; }
    int c = i / 384, k = i - c * 384;
    int nb = c >> 7, n = c & 127;
    int kc = k >> 5, k5 = k & 31;
    int gl = k5 >> 4, sl = SLOT((k5 >> 1) & 7);
    size_t hid = ((size_t)((nb * 12 + kc) * 128 + n) * 16 + gl * 8 + sl) * 2 + (k5 & 1);
    dst[hid] = __float2half_rn(src[(size_t)c * 384 + k]);
}

__global__ void prep_bm(const float* __restrict__ mask, const float* __restrict__ table,
                        const int* __restrict__ ridx) {
    const int wv = blockIdx.x, h = blockIdx.y;
    float* dst = g_bm + (size_t)(wv * NH + h) * (NTOK * NTOK);
    for (int i = threadIdx.x; i < NTOK * NTOK; i += blockDim.x)
        dst[i] = table[ridx[i] * NH + h] + mask[wv * (NTOK * NTOK) + i];
}

/* ---------------- fp16 mma GEMM: 128 rows x (nbN*128) cols, K=384 ----------------
   mode 0: A=x fp32 (converted), W=g_wq, epilogue -> packed g_q/g_k/g_vt
   mode 1: A=g_ob (raw copy),    W=g_wp, epilogue -> out fp32 + bias        */
__global__ __launch_bounds__(256, 2)
void gemm_mm(const float* __restrict__ Aext, const float* __restrict__ bias,
             float* __restrict__ Cext, int nbN, int mode) {
    extern __shared__ uint32_t sm[];
    const int tid = threadIdx.x, warp = tid >> 5, lane = tid & 31;
    const int lg = lane >> 2, lt = lane & 3;
    const int warpm = warp & 3, warpn = warp >> 2;
    const int mbase = blockIdx.x * 128;
    const uint32_t* W = mode ? g_wp : g_wq;

    /* stage A */
    if (mode == 0) {
        for (int i = tid; i < 12288; i += 256) {
            int r = i / 96, c4 = i - r * 96;
            float4 v = *reinterpret_cast<const float4*>(Aext + (size_t)(mbase + r) * 384 + c4 * 4);
            int g = c4 >> 2, p0 = (c4 << 1) & 7;
            sm[r * GA_STRIDE + g * 8 + SLOT(p0)]     = h2u(v.x, v.y);
            sm[r * GA_STRIDE + g * 8 + SLOT(p0 + 1)] = h2u(v.z, v.w);
        }
    } else {
        const float4* s4 = reinterpret_cast<const float4*>(g_ob + (size_t)mbase * 196);
        float4* d4 = reinterpret_cast<float4*>(sm);
        for (int i = tid; i < 6272; i += 256) d4[i] = s4[i];
    }

    /* precompute rows / (win,t) */
    int rr[4], win[4], tt[4];
    #pragma unroll
    for (int q = 0; q < 4; q++) {
        rr[q] = mbase + warpm * 32 + lg + q * 8;
        win[q] = rr[q] / 49;
        tt[q] = rr[q] - win[q] * 49;
    }

    #pragma unroll 1
    for (int nb = 0; nb < nbN; nb++) {
        float acc[2][8][4];
        #pragma unroll
        for (int a = 0; a < 2; a++)
            #pragma unroll
            for (int f = 0; f < 8; f++)
                #pragma unroll
                for (int c = 0; c < 4; c++) acc[a][f][c] = 0.f;

        const uint32_t* Wnb = W + (size_t)nb * 12 * 2048;
        #pragma unroll 1
        for (int kc = 0; kc < 12; kc++) {
            __syncthreads();
            {
                const float4* s4 = reinterpret_cast<const float4*>(Wnb + kc * 2048);
                #pragma unroll
                for (int i = tid; i < 512; i += 256) {
                    int col = i >> 2, q = i & 3;
                    *reinterpret_cast<float4*>(&sm[GB_OFF + col * 20 + q * 4]) = s4[i];
                }
            }
            __syncthreads();
            #pragma unroll
            for (int gl = 0; gl < 2; gl++) {
                const int ab = (kc * 2 + gl) * 8 + 2 * lt;
                const int R = warpm * 32 + lg;
                uint2 lo0 = *reinterpret_cast<const uint2*>(&sm[R * GA_STRIDE + ab]);
                uint2 hi0 = *reinterpret_cast<const uint2*>(&sm[(R + 8) * GA_STRIDE + ab]);
                uint2 lo1 = *reinterpret_cast<const uint2*>(&sm[(R + 16) * GA_STRIDE + ab]);
                uint2 hi1 = *reinterpret_cast<const uint2*>(&sm[(R + 24) * GA_STRIDE + ab]);
                #pragma unroll
                for (int nf = 0; nf < 8; nf++) {
                    int n = warpn * 64 + nf * 8 + lg;
                    uint2 bb = *reinterpret_cast<const uint2*>(&sm[GB_OFF + n * 20 + gl * 8 + 2 * lt]);
                    mma16(acc[0][nf], lo0.x, hi0.x, lo0.y, hi0.y, bb.x, bb.y);
                    mma16(acc[1][nf], lo1.x, hi1.x, lo1.y, hi1.y, bb.x, bb.y);
                }
            }
        }

        /* epilogue */
        if (mode == 1) {
            #pragma unroll
            for (int nf = 0; nf < 8; nf++) {
                int col = nb * 128 + warpn * 64 + nf * 8 + lt * 2;
                float b0 = __ldg(&bias[col]), b1 = __ldg(&bias[col + 1]);
                #pragma unroll
                for (int mt = 0; mt < 2; mt++) {
                    *reinterpret_cast<float2*>(&Cext[(size_t)rr[mt * 2] * 384 + col]) =
                        make_float2(acc[mt][nf][0] + b0, acc[mt][nf][1] + b1);
                    *reinterpret_cast<float2*>(&Cext[(size_t)rr[mt * 2 + 1] * 384 + col]) =
                        make_float2(acc[mt][nf][2] + b0, acc[mt][nf][3] + b1);
                }
            }
        } else {
            const int part = (nb >= 6) ? 2 : ((nb >= 3) ? 1 : 0);
            const int wcb = (nb - part * 3) * 128 + warpn * 64;
            #pragma unroll
            for (int nf = 0; nf < 8; nf++) {
                int wcol = wcb + nf * 8 + lt * 2;
                int h = wcol >> 5, c32 = wcol & 31;
                int gcol = nb * 128 + warpn * 64 + nf * 8 + lt * 2;
                float b0 = __ldg(&bias[gcol]), b1 = __ldg(&bias[gcol + 1]);
                int gA = c32 >> 4, slA = SLOT((c32 >> 1) & 7);
                #pragma unroll
                for (int q = 0; q < 4; q++) {
                    float v0 = acc[q >> 1][nf][(q & 1) * 2 + 0] + b0;
                    float v1 = acc[q >> 1][nf][(q & 1) * 2 + 1] + b1;
                    size_t hd = (size_t)(win[q] * 12 + h);
                    if (part == 0) {
                        g_q[hd * 980 + tt[q] * 20 + gA * 8 + slA] = h2u(v0 * SCALE, v1 * SCALE);
                    } else if (part == 1) {
                        g_k[hd * 980 + tt[q] * 20 + gA * 8 + slA] = h2u(v0, v1);
                    } else {
                        int gt = tt[q] >> 4, slt = SLOT((tt[q] >> 1) & 7);
                        __half* vtb = (__half*)(g_vt + hd * 1152);
                        int u0 = c32 * 36 + gt * 8 + slt;
                        vtb[u0 * 2 + (tt[q] & 1)] = __float2half_rn(v0);
                        vtb[(u0 + 36) * 2 + (tt[q] & 1)] = __float2half_rn(v1);
                    }
                }
            }
        }
    }
}

/* ---------------- attention (fp16 mma, cp.async staged) ---------------- */
__device__ __forceinline__ void copy_head(uint32_t smb, int b, int h, int buf, int tid) {
    size_t idx = (size_t)(b * 12 + h);
    const float4* sq = reinterpret_cast<const float4*>(g_q + idx * 980);
    const float4* sk = reinterpret_cast<const float4*>(g_k + idx * 980);
    const float4* sv = reinterpret_cast<const float4*>(g_vt + idx * 1152);
    uint32_t d0 = smb + buf * (ABUF * 4);
    for (int i = tid; i < 778; i += 384) {
        if (i < 245)      cpa16(d0 + AQ_OFF * 4 + i * 16, sq + i);
        else if (i < 490) cpa16(d0 + AK_OFF * 4 + (i - 245) * 16, sk + (i - 245));
        else              cpa16(d0 + AVT_OFF * 4 + (i - 490) * 16, sv + (i - 490));
    }
}

__global__ __launch_bounds__(384, 2)
void attn_kernel() {
    extern __shared__ uint32_t sm[];
    float* smf = reinterpret_cast<float*>(sm);
    const uint32_t smb = smem_u32(sm);
    const int b = blockIdx.x;
    const int wi = b & (NWIN - 1);
    const int tid = threadIdx.x, warp = tid >> 5, lane = tid & 31;
    const int lg = lane >> 2, lt = lane & 3;
    const int mt = warp & 3, ng = warp >> 2;
    const int r0 = mt * 16 + lg, r1 = r0 + 8;
    const bool ok0 = r0 < NTOK, ok1 = r1 < NTOK;

    for (int i = tid; i < 2304; i += 384) sm[AP_OFF + i] = 0;   /* zero P */
    copy_head(smb, b, 0, 0, tid);
    CP_COMMIT();

    #pragma unroll 1
    for (int h = 0; h < NH; h++) {
        __syncthreads();
        const int cur = h & 1;
        const uint32_t B0 = cur * ABUF;
        if (h < 11) { copy_head(smb, b, h + 1, cur ^ 1, tid); CP_COMMIT(); CP_WAIT(1); }
        else        { CP_WAIT(0); }
        /* zero pads: K rows 49..55, VT token pads */
        for (int i = tid; i < 140; i += 384) sm[B0 + AK_OFF + 980 + i] = 0;
        if (tid < 224) { int col = tid >> 3, j = tid & 7; if (j < 7) sm[B0 + AVT_OFF + col * 36 + 25 + j] = 0; }
        if (tid >= 224 && tid < 256)
            reinterpret_cast<__half*>(&sm[B0 + AVT_OFF + (tid - 224) * 36 + 24])[1] = __float2half(0.f);
        __syncthreads();

        /* S = q @ k^T (K=32) */
        {
            float sacc[3][4];
            #pragma unroll
            for (int i = 0; i < 3; i++)
                #pragma unroll
                for (int j = 0; j < 4; j++) sacc[i][j] = 0.f;
            const int ntn = (ng == 2) ? 3 : 2;
            const int ntb = (ng == 2) ? 4 : ng * 2;
            #pragma unroll
            for (int g = 0; g < 2; g++) {
                uint2 qlo = make_uint2(0u, 0u), qhi = qlo;
                if (ok0) qlo = *reinterpret_cast<const uint2*>(&sm[B0 + AQ_OFF + r0 * 20 + g * 8 + 2 * lt]);
                if (ok1) qhi = *reinterpret_cast<const uint2*>(&sm[B0 + AQ_OFF + r1 * 20 + g * 8 + 2 * lt]);
                #pragma unroll
                for (int j = 0; j < 3; j++) {
                    if (j < ntn) {
                        int n = (ntb + j) * 8 + lg;
                        uint2 kb = *reinterpret_cast<const uint2*>(&sm[B0 + AK_OFF + n * 20 + g * 8 + 2 * lt]);
                        mma16(sacc[j], qlo.x, qhi.x, qlo.y, qhi.y, kb.x, kb.y);
                    }
                }
            }
            const float* bmh = g_bm + (size_t)(wi * NH + h) * (NTOK * NTOK);
            #pragma unroll
            for (int j = 0; j < 3; j++) {
                if (j < ntn) {
                    #pragma unroll
                    for (int ci = 0; ci < 4; ci++) {
                        int r = (ci & 2) ? r1 : r0;
                        int cc = (ntb + j) * 8 + (lt << 1) + (ci & 1);
                        float v = sacc[j][ci];
                        if (r < NTOK && cc < NTOK) v += bmh[r * NTOK + cc];
                        smf[AS_OFF + r * 60 + cc] = v;
                    }
                }
            }
        }
        __syncthreads();

        /* softmax rows 0..48 -> packed fp16 P */
        for (int r = warp; r < NTOK; r += 12) {
            float v0 = smf[AS_OFF + r * 60 + lane];
            float v1 = (lane + 32 < NTOK) ? smf[AS_OFF + r * 60 + lane + 32] : -1e30f;
            float mx = fmaxf(v0, v1);
            #pragma unroll
            for (int o = 16; o > 0; o >>= 1) mx = fmaxf(mx, __shfl_xor_sync(0xffffffffu, mx, o));
            float e0 = __expf(v0 - mx);
            float e1 = (lane + 32 < NTOK) ? __expf(v1 - mx) : 0.f;
            float s = e0 + e1;
            #pragma unroll
            for (int o = 16; o > 0; o >>= 1) s += __shfl_xor_sync(0xffffffffu, s, o);
            float inv = 1.0f / s;
            int c = lane;
            reinterpret_cast<__half*>(&sm[AP_OFF + r * 36 + (c >> 4) * 8 + SLOT((c >> 1) & 7)])[c & 1] =
                __float2half_rn(e0 * inv);
            int c2 = lane + 32;
            if (c2 < 56) {
                float pv = (c2 < NTOK) ? e1 * inv : 0.f;
                reinterpret_cast<__half*>(&sm[AP_OFF + r * 36 + (c2 >> 4) * 8 + SLOT((c2 >> 1) & 7)])[c2 & 1] =
                    __float2half_rn(pv);
            }
        }
        __syncthreads();

        /* O = P @ V (K=64 padded) -> g_ob packed */
        {
            float oacc[2][4];
            #pragma unroll
            for (int i = 0; i < 2; i++)
                #pragma unroll
                for (int j = 0; j < 4; j++) oacc[i][j] = 0.f;
            const int non = (ng == 2) ? 2 : 1;
            const int nob = (ng == 2) ? 2 : ng;
            #pragma unroll
            for (int g = 0; g < 4; g++) {
                uint2 plo = *reinterpret_cast<const uint2*>(&sm[AP_OFF + r0 * 36 + g * 8 + 2 * lt]);
                uint2 phi = *reinterpret_cast<const uint2*>(&sm[AP_OFF + r1 * 36 + g * 8 + 2 * lt]);
                #pragma unroll
                for (int j = 0; j < 2; j++) {
                    if (j < non) {
                        int n = (nob + j) * 8 + lg;
                        uint2 vb = *reinterpret_cast<const uint2*>(&sm[B0 + AVT_OFF + n * 36 + g * 8 + 2 * lt]);
                        mma16(oacc[j], plo.x, phi.x, plo.y, phi.y, vb.x, vb.y);
                    }
                }
            }
            #pragma unroll
            for (int j = 0; j < 2; j++) {
                if (j < non) {
                    int cc = (nob + j) * 8 + lt * 2;
                    int col = h * 32 + cc;
                    int gA = col >> 4, slA = SLOT((col >> 1) & 7);
                    if (ok0)
                        g_ob[(size_t)(b * NTOK + r0) * 196 + gA * 8 + slA] = h2u(oacc[j][0], oacc[j][1]);
                    if (ok1)
                        g_ob[(size_t)(b * NTOK + r1) * 196 + gA * 8 + slA] = h2u(oacc[j][2], oacc[j][3]);
                }
            }
        }
    }
}

/* ---------------- launcher ---------------- */
extern "C" void kernel_launch(void* const* d_in, const int* in_sizes, int n_in,
                              void* d_out, int out_size) {
    const float* x      = (const float*)d_in[0];
    const float* mask   = (const float*)d_in[1];
    const float* table  = (const float*)d_in[2];
    const float* qkv_w  = (const float*)d_in[3];
    const float* qkv_b  = (const float*)d_in[4];
    const float* proj_w = (const float*)d_in[5];
    const float* proj_b = (const float*)d_in[6];
    const int*   ridx   = (const int*)d_in[7];
    float* out = (float*)d_out;

    cudaFuncSetAttribute(gemm_mm, cudaFuncAttributeMaxDynamicSharedMemorySize, GSMEM_BYTES);
    cudaFuncSetAttribute(attn_kernel, cudaFuncAttributeMaxDynamicSharedMemorySize, ASMEM_BYTES);

    prep_pack<<<2304, 256>>>(qkv_w, proj_w);
    prep_bm<<<dim3(NWIN, NH), 128>>>(mask, table, ridx);
    gemm_mm<<<NMT, 256, GSMEM_BYTES>>>(x, qkv_b, nullptr, 9, 0);
    attn_kernel<<<NBLK, 384, ASMEM_BYTES>>>();
    gemm_mm<<<NMT, 256, GSMEM_BYTES>>>(nullptr, proj_b, out, 3, 1);
}

// round 7
// speedup vs baseline: 1.0308x; 1.0308x over previous
#include <cuda_runtime.h>
#include <cuda_fp16.h>
#include <cstdint>

#define NTOK 49
#define NH   12
#define NWIN 64
#define NBLK 8192
#define NROWS (NBLK * NTOK)
#define NMT  3136
#define SCALE 0.17677669529663687f

/* gemm smem (u32): A [128][196], then 4 B buffers [128][20] each (2560 u32) */
#define GA_STRIDE 196
#define GB_OFF    25088
#define GSMEM_U32 (GB_OFF + 4 * 2560)
#define GSMEM_BYTES (GSMEM_U32 * 4)   /* 141312 */

/* attn smem (u32): 2 qkv buffers, P, S */
#define ABUF 3252
#define AQ_OFF  0
#define AK_OFF  980
#define AVT_OFF 2100
#define AP_OFF  6504
#define AS_OFF  8808
#define ASMEM_U32 12648
#define ASMEM_BYTES (ASMEM_U32 * 4)

/* ---------------- device scratch ---------------- */
__device__ uint32_t g_wq[9 * 12 * 2048];
__device__ uint32_t g_wp[3 * 12 * 2048];
__device__ uint32_t g_q [(size_t)NBLK * NH * 980];
__device__ uint32_t g_k [(size_t)NBLK * NH * 980];
__device__ uint32_t g_vt[(size_t)NBLK * NH * 1152];
__device__ uint32_t g_ob[(size_t)NROWS * 196];
__device__ float    g_bm[NWIN * NH * NTOK * NTOK];

/* ---------------- helpers ---------------- */
__device__ __forceinline__ int SLOT(int p7) { return ((p7 & 3) << 1) | (p7 >> 2); }

__device__ __forceinline__ uint32_t smem_u32(const void* p) {
    uint32_t a;
    asm("{ .reg .u64 t; cvta.to.shared.u64 t, %1; cvt.u32.u64 %0, t; }" : "=r"(a) : "l"(p));
    return a;
}
__device__ __forceinline__ uint32_t h2u(float a, float b) {
    __half2 h = __floats2half2_rn(a, b);
    return *reinterpret_cast<uint32_t*>(&h);
}
__device__ __forceinline__ void cpa16(uint32_t dst, const void* src) {
    asm volatile("cp.async.ca.shared.global [%0], [%1], 16;"
                 :: "r"(dst), "l"(__cvta_generic_to_global(src)));
}
#define CP_COMMIT() asm volatile("cp.async.commit_group;" ::: "memory")
#define CP_WAIT(n)  asm volatile("cp.async.wait_group %0;" :: "n"(n) : "memory")

__device__ __forceinline__ void mma16(float* c, uint32_t a0, uint32_t a1, uint32_t a2,
                                      uint32_t a3, uint32_t b0, uint32_t b1) {
    asm volatile(
        "mma.sync.aligned.m16n8k16.row.col.f32.f16.f16.f32 "
        "{%0,%1,%2,%3},{%4,%5,%6,%7},{%8,%9},{%0,%1,%2,%3};"
        : "+f"(c[0]), "+f"(c[1]), "+f"(c[2]), "+f"(c[3])
        : "r"(a0), "r"(a1), "r"(a2), "r"(a3), "r"(b0), "r"(b1));
}

/* ---------------- prep kernels ---------------- */
__global__ void prep_pack(const float* __restrict__ qkv_w, const float* __restrict__ proj_w) {
    int i = blockIdx.x * 256 + threadIdx.x;
    const float* src;
    __half* dst;
    if (i < 1152 * 384) { src = qkv_w; dst = (__half*)g_wq; }
    else { i -= 1152 * 384; src = proj_w; dst = (__half*)g_wp; }
    int c = i / 384, k = i - c * 384;
    int nb = c >> 7, n = c & 127;
    int kc = k >> 5, k5 = k & 31;
    int gl = k5 >> 4, sl = SLOT((k5 >> 1) & 7);
    size_t hid = ((size_t)((nb * 12 + kc) * 128 + n) * 16 + gl * 8 + sl) * 2 + (k5 & 1);
    dst[hid] = __float2half_rn(src[(size_t)c * 384 + k]);
}

__global__ void prep_bm(const float* __restrict__ mask, const float* __restrict__ table,
                        const int* __restrict__ ridx) {
    const int wv = blockIdx.x, h = blockIdx.y;
    float* dst = g_bm + (size_t)(wv * NH + h) * (NTOK * NTOK);
    for (int i = threadIdx.x; i < NTOK * NTOK; i += blockDim.x)
        dst[i] = table[ridx[i] * NH + h] + mask[wv * (NTOK * NTOK) + i];
}

/* ---------------- fp16 GEMM, cp.async-pipelined B (4 bufs, depth 2) ---------------- */
__global__ __launch_bounds__(256, 1)
void gemm_mm(const float* __restrict__ Aext, const float* __restrict__ bias,
             float* __restrict__ Cext, int nbN, int mode) {
    extern __shared__ uint32_t sm[];
    const int tid = threadIdx.x, warp = tid >> 5, lane = tid & 31;
    const int lg = lane >> 2, lt = lane & 3;
    const int warpm = warp & 3, warpn = warp >> 2;
    const int mbase = blockIdx.x * 128;
    const uint32_t* W = mode ? g_wp : g_wq;
    const uint32_t smb = smem_u32(sm);
    const int NC = nbN * 12;
    const uint32_t dBq = ((tid >> 2) * 20 + (tid & 3) * 4) * 4;   /* per-thread B dst (bytes) */

    /* stage A */
    if (mode == 0) {
        for (int i = tid; i < 12288; i += 256) {
            int r = i / 96, c4 = i - r * 96;
            float4 v = *reinterpret_cast<const float4*>(Aext + (size_t)(mbase + r) * 384 + c4 * 4);
            int g = c4 >> 2, p0 = (c4 << 1) & 7;
            sm[r * GA_STRIDE + g * 8 + SLOT(p0)]     = h2u(v.x, v.y);
            sm[r * GA_STRIDE + g * 8 + SLOT(p0 + 1)] = h2u(v.z, v.w);
        }
    } else {
        const float4* s4 = reinterpret_cast<const float4*>(g_ob + (size_t)mbase * 196);
        float4* d4 = reinterpret_cast<float4*>(sm);
        for (int i = tid; i < 6272; i += 256) d4[i] = s4[i];
    }

    /* B pipeline prologue: chunks 0,1 */
    #pragma unroll
    for (int p = 0; p < 2; p++) {
        const uint4* s0 = reinterpret_cast<const uint4*>(W + (size_t)p * 2048);
        uint32_t d = smb + (GB_OFF + p * 2560) * 4 + dBq;
        cpa16(d, s0 + tid);
        cpa16(d + 1280 * 4, s0 + 256 + tid);
        CP_COMMIT();
    }

    int rr[4], win[4], tt[4];
    #pragma unroll
    for (int q = 0; q < 4; q++) {
        rr[q] = mbase + warpm * 32 + lg + q * 8;
        win[q] = rr[q] / 49;
        tt[q] = rr[q] - win[q] * 49;
    }

    #pragma unroll 1
    for (int nb = 0; nb < nbN; nb++) {
        float acc[2][8][4];
        #pragma unroll
        for (int a = 0; a < 2; a++)
            #pragma unroll
            for (int f = 0; f < 8; f++)
                #pragma unroll
                for (int c = 0; c < 4; c++) acc[a][f][c] = 0.f;

        #pragma unroll 1
        for (int kc = 0; kc < 12; kc++) {
            const int c = nb * 12 + kc;
            if (c + 2 < NC) {
                const uint4* s0 = reinterpret_cast<const uint4*>(W + (size_t)(c + 2) * 2048);
                uint32_t d = smb + (GB_OFF + ((c + 2) & 3) * 2560) * 4 + dBq;
                cpa16(d, s0 + tid);
                cpa16(d + 1280 * 4, s0 + 256 + tid);
            }
            CP_COMMIT();
            CP_WAIT(2);
            __syncthreads();
            const uint32_t* Bb = sm + GB_OFF + (c & 3) * 2560;
            #pragma unroll
            for (int gl = 0; gl < 2; gl++) {
                const int ab = (kc * 2 + gl) * 8 + 2 * lt;
                const int R = warpm * 32 + lg;
                uint2 lo0 = *reinterpret_cast<const uint2*>(&sm[R * GA_STRIDE + ab]);
                uint2 hi0 = *reinterpret_cast<const uint2*>(&sm[(R + 8) * GA_STRIDE + ab]);
                uint2 lo1 = *reinterpret_cast<const uint2*>(&sm[(R + 16) * GA_STRIDE + ab]);
                uint2 hi1 = *reinterpret_cast<const uint2*>(&sm[(R + 24) * GA_STRIDE + ab]);
                #pragma unroll
                for (int nf = 0; nf < 8; nf++) {
                    int n = warpn * 64 + nf * 8 + lg;
                    uint2 bb = *reinterpret_cast<const uint2*>(&Bb[n * 20 + gl * 8 + 2 * lt]);
                    mma16(acc[0][nf], lo0.x, hi0.x, lo0.y, hi0.y, bb.x, bb.y);
                    mma16(acc[1][nf], lo1.x, hi1.x, lo1.y, hi1.y, bb.x, bb.y);
                }
            }
        }

        /* epilogue (same as R5) */
        if (mode == 1) {
            #pragma unroll
            for (int nf = 0; nf < 8; nf++) {
                int col = nb * 128 + warpn * 64 + nf * 8 + lt * 2;
                float b0 = __ldg(&bias[col]), b1 = __ldg(&bias[col + 1]);
                #pragma unroll
                for (int mt = 0; mt < 2; mt++) {
                    *reinterpret_cast<float2*>(&Cext[(size_t)rr[mt * 2] * 384 + col]) =
                        make_float2(acc[mt][nf][0] + b0, acc[mt][nf][1] + b1);
                    *reinterpret_cast<float2*>(&Cext[(size_t)rr[mt * 2 + 1] * 384 + col]) =
                        make_float2(acc[mt][nf][2] + b0, acc[mt][nf][3] + b1);
                }
            }
        } else {
            const int part = (nb >= 6) ? 2 : ((nb >= 3) ? 1 : 0);
            const int wcb = (nb - part * 3) * 128 + warpn * 64;
            #pragma unroll
            for (int nf = 0; nf < 8; nf++) {
                int wcol = wcb + nf * 8 + lt * 2;
                int h = wcol >> 5, c32 = wcol & 31;
                int gcol = nb * 128 + warpn * 64 + nf * 8 + lt * 2;
                float b0 = __ldg(&bias[gcol]), b1 = __ldg(&bias[gcol + 1]);
                int gA = c32 >> 4, slA = SLOT((c32 >> 1) & 7);
                #pragma unroll
                for (int q = 0; q < 4; q++) {
                    float v0 = acc[q >> 1][nf][(q & 1) * 2 + 0] + b0;
                    float v1 = acc[q >> 1][nf][(q & 1) * 2 + 1] + b1;
                    size_t hd = (size_t)(win[q] * 12 + h);
                    if (part == 0) {
                        g_q[hd * 980 + tt[q] * 20 + gA * 8 + slA] = h2u(v0 * SCALE, v1 * SCALE);
                    } else if (part == 1) {
                        g_k[hd * 980 + tt[q] * 20 + gA * 8 + slA] = h2u(v0, v1);
                    } else {
                        int gt = tt[q] >> 4, slt = SLOT((tt[q] >> 1) & 7);
                        __half* vtb = (__half*)(g_vt + hd * 1152);
                        int u0 = c32 * 36 + gt * 8 + slt;
                        vtb[u0 * 2 + (tt[q] & 1)] = __float2half_rn(v0);
                        vtb[(u0 + 36) * 2 + (tt[q] & 1)] = __float2half_rn(v1);
                    }
                }
            }
        }
    }
}

/* ---------------- attention (identical to R5 passing version) ---------------- */
__device__ __forceinline__ void copy_head(uint32_t smb, int b, int h, int buf, int tid) {
    size_t idx = (size_t)(b * 12 + h);
    const float4* sq = reinterpret_cast<const float4*>(g_q + idx * 980);
    const float4* sk = reinterpret_cast<const float4*>(g_k + idx * 980);
    const float4* sv = reinterpret_cast<const float4*>(g_vt + idx * 1152);
    uint32_t d0 = smb + buf * (ABUF * 4);
    for (int i = tid; i < 778; i += 384) {
        if (i < 245)      cpa16(d0 + AQ_OFF * 4 + i * 16, sq + i);
        else if (i < 490) cpa16(d0 + AK_OFF * 4 + (i - 245) * 16, sk + (i - 245));
        else              cpa16(d0 + AVT_OFF * 4 + (i - 490) * 16, sv + (i - 490));
    }
}

__global__ __launch_bounds__(384, 2)
void attn_kernel() {
    extern __shared__ uint32_t sm[];
    float* smf = reinterpret_cast<float*>(sm);
    const uint32_t smb = smem_u32(sm);
    const int b = blockIdx.x;
    const int wi = b & (NWIN - 1);
    const int tid = threadIdx.x, warp = tid >> 5, lane = tid & 31;
    const int lg = lane >> 2, lt = lane & 3;
    const int mt = warp & 3, ng = warp >> 2;
    const int r0 = mt * 16 + lg, r1 = r0 + 8;
    const bool ok0 = r0 < NTOK, ok1 = r1 < NTOK;

    for (int i = tid; i < 2304; i += 384) sm[AP_OFF + i] = 0;
    copy_head(smb, b, 0, 0, tid);
    CP_COMMIT();

    #pragma unroll 1
    for (int h = 0; h < NH; h++) {
        __syncthreads();
        const int cur = h & 1;
        const uint32_t B0 = cur * ABUF;
        if (h < 11) { copy_head(smb, b, h + 1, cur ^ 1, tid); CP_COMMIT(); CP_WAIT(1); }
        else        { CP_WAIT(0); }
        for (int i = tid; i < 140; i += 384) sm[B0 + AK_OFF + 980 + i] = 0;
        if (tid < 224) { int col = tid >> 3, j = tid & 7; if (j < 7) sm[B0 + AVT_OFF + col * 36 + 25 + j] = 0; }
        if (tid >= 224 && tid < 256)
            reinterpret_cast<__half*>(&sm[B0 + AVT_OFF + (tid - 224) * 36 + 24])[1] = __float2half(0.f);
        __syncthreads();

        {
            float sacc[3][4];
            #pragma unroll
            for (int i = 0; i < 3; i++)
                #pragma unroll
                for (int j = 0; j < 4; j++) sacc[i][j] = 0.f;
            const int ntn = (ng == 2) ? 3 : 2;
            const int ntb = (ng == 2) ? 4 : ng * 2;
            #pragma unroll
            for (int g = 0; g < 2; g++) {
                uint2 qlo = make_uint2(0u, 0u), qhi = qlo;
                if (ok0) qlo = *reinterpret_cast<const uint2*>(&sm[B0 + AQ_OFF + r0 * 20 + g * 8 + 2 * lt]);
                if (ok1) qhi = *reinterpret_cast<const uint2*>(&sm[B0 + AQ_OFF + r1 * 20 + g * 8 + 2 * lt]);
                #pragma unroll
                for (int j = 0; j < 3; j++) {
                    if (j < ntn) {
                        int n = (ntb + j) * 8 + lg;
                        uint2 kb = *reinterpret_cast<const uint2*>(&sm[B0 + AK_OFF + n * 20 + g * 8 + 2 * lt]);
                        mma16(sacc[j], qlo.x, qhi.x, qlo.y, qhi.y, kb.x, kb.y);
                    }
                }
            }
            const float* bmh = g_bm + (size_t)(wi * NH + h) * (NTOK * NTOK);
            #pragma unroll
            for (int j = 0; j < 3; j++) {
                if (j < ntn) {
                    #pragma unroll
                    for (int ci = 0; ci < 4; ci++) {
                        int r = (ci & 2) ? r1 : r0;
                        int cc = (ntb + j) * 8 + (lt << 1) + (ci & 1);
                        float v = sacc[j][ci];
                        if (r < NTOK && cc < NTOK) v += bmh[r * NTOK + cc];
                        smf[AS_OFF + r * 60 + cc] = v;
                    }
                }
            }
        }
        __syncthreads();

        for (int r = warp; r < NTOK; r += 12) {
            float v0 = smf[AS_OFF + r * 60 + lane];
            float v1 = (lane + 32 < NTOK) ? smf[AS_OFF + r * 60 + lane + 32] : -1e30f;
            float mx = fmaxf(v0, v1);
            #pragma unroll
            for (int o = 16; o > 0; o >>= 1) mx = fmaxf(mx, __shfl_xor_sync(0xffffffffu, mx, o));
            float e0 = __expf(v0 - mx);
            float e1 = (lane + 32 < NTOK) ? __expf(v1 - mx) : 0.f;
            float s = e0 + e1;
            #pragma unroll
            for (int o = 16; o > 0; o >>= 1) s += __shfl_xor_sync(0xffffffffu, s, o);
            float inv = 1.0f / s;
            int c = lane;
            reinterpret_cast<__half*>(&sm[AP_OFF + r * 36 + (c >> 4) * 8 + SLOT((c >> 1) & 7)])[c & 1] =
                __float2half_rn(e0 * inv);
            int c2 = lane + 32;
            if (c2 < 56) {
                float pv = (c2 < NTOK) ? e1 * inv : 0.f;
                reinterpret_cast<__half*>(&sm[AP_OFF + r * 36 + (c2 >> 4) * 8 + SLOT((c2 >> 1) & 7)])[c2 & 1] =
                    __float2half_rn(pv);
            }
        }
        __syncthreads();

        {
            float oacc[2][4];
            #pragma unroll
            for (int i = 0; i < 2; i++)
                #pragma unroll
                for (int j = 0; j < 4; j++) oacc[i][j] = 0.f;
            const int non = (ng == 2) ? 2 : 1;
            const int nob = (ng == 2) ? 2 : ng;
            #pragma unroll
            for (int g = 0; g < 4; g++) {
                uint2 plo = *reinterpret_cast<const uint2*>(&sm[AP_OFF + r0 * 36 + g * 8 + 2 * lt]);
                uint2 phi = *reinterpret_cast<const uint2*>(&sm[AP_OFF + r1 * 36 + g * 8 + 2 * lt]);
                #pragma unroll
                for (int j = 0; j < 2; j++) {
                    if (j < non) {
                        int n = (nob + j) * 8 + lg;
                        uint2 vb = *reinterpret_cast<const uint2*>(&sm[B0 + AVT_OFF + n * 36 + g * 8 + 2 * lt]);
                        mma16(oacc[j], plo.x, phi.x, plo.y, phi.y, vb.x, vb.y);
                    }
                }
            }
            #pragma unroll
            for (int j = 0; j < 2; j++) {
                if (j < non) {
                    int cc = (nob + j) * 8 + lt * 2;
                    int col = h * 32 + cc;
                    int gA = col >> 4, slA = SLOT((col >> 1) & 7);
                    if (ok0)
                        g_ob[(size_t)(b * NTOK + r0) * 196 + gA * 8 + slA] = h2u(oacc[j][0], oacc[j][1]);
                    if (ok1)
                        g_ob[(size_t)(b * NTOK + r1) * 196 + gA * 8 + slA] = h2u(oacc[j][2], oacc[j][3]);
                }
            }
        }
    }
}

/* ---------------- launcher ---------------- */
extern "C" void kernel_launch(void* const* d_in, const int* in_sizes, int n_in,
                              void* d_out, int out_size) {
    const float* x      = (const float*)d_in[0];
    const float* mask   = (const float*)d_in[1];
    const float* table  = (const float*)d_in[2];
    const float* qkv_w  = (const float*)d_in[3];
    const float* qkv_b  = (const float*)d_in[4];
    const float* proj_w = (const float*)d_in[5];
    const float* proj_b = (const float*)d_in[6];
    const int*   ridx   = (const int*)d_in[7];
    float* out = (float*)d_out;

    cudaFuncSetAttribute(gemm_mm, cudaFuncAttributeMaxDynamicSharedMemorySize, GSMEM_BYTES);
    cudaFuncSetAttribute(attn_kernel, cudaFuncAttributeMaxDynamicSharedMemorySize, ASMEM_BYTES);

    prep_pack<<<2304, 256>>>(qkv_w, proj_w);
    prep_bm<<<dim3(NWIN, NH), 128>>>(mask, table, ridx);
    gemm_mm<<<NMT, 256, GSMEM_BYTES>>>(x, qkv_b, nullptr, 9, 0);
    attn_kernel<<<NBLK, 384, ASMEM_BYTES>>>();
    gemm_mm<<<NMT, 256, GSMEM_BYTES>>>(nullptr, proj_b, out, 3, 1);
}

// round 9
// speedup vs baseline: 1.2740x; 1.2360x over previous
#include <cuda_runtime.h>
#include <cuda_fp16.h>
#include <cstdint>

#define NTOK 49
#define NH   12
#define NWIN 64
#define NBLK 8192
#define NROWS (NBLK * NTOK)
#define NMT  3136
#define SCALE 0.17677669529663687f

/* gemm smem (u32): A [128][196], then 4 B buffers [128][20] each (2560 u32) */
#define GA_STRIDE 196
#define GB_OFF    25088
#define GSMEM_U32 (GB_OFF + 4 * 2560)
#define GSMEM_BYTES (GSMEM_U32 * 4)   /* 141312 */

/* ---------------- device scratch ---------------- */
__device__ uint32_t g_wq[9 * 12 * 2048];
__device__ uint32_t g_wp[3 * 12 * 2048];
__device__ uint32_t g_q [(size_t)NBLK * NH * 980 + 512];   /* +slack: frag reads of pad rows */
__device__ uint32_t g_k [(size_t)NBLK * NH * 980 + 512];
__device__ uint32_t g_vt[(size_t)NBLK * NH * 1152];
__device__ uint32_t g_ob[(size_t)NROWS * 196];
__device__ float    g_bm[NWIN * NH * NTOK * 56];           /* stride 56 (aligned float2) */

/* ---------------- helpers ---------------- */
__device__ __forceinline__ int SLOT(int p7) { return ((p7 & 3) << 1) | (p7 >> 2); }

__device__ __forceinline__ uint32_t smem_u32(const void* p) {
    uint32_t a;
    asm("{ .reg .u64 t; cvta.to.shared.u64 t, %1; cvt.u32.u64 %0, t; }" : "=r"(a) : "l"(p));
    return a;
}
__device__ __forceinline__ uint32_t h2u(float a, float b) {
    __half2 h = __floats2half2_rn(a, b);
    return *reinterpret_cast<uint32_t*>(&h);
}
__device__ __forceinline__ void cpa16(uint32_t dst, const void* src) {
    asm volatile("cp.async.ca.shared.global [%0], [%1], 16;"
                 :: "r"(dst), "l"(__cvta_generic_to_global(src)));
}
#define CP_COMMIT() asm volatile("cp.async.commit_group;" ::: "memory")
#define CP_WAIT(n)  asm volatile("cp.async.wait_group %0;" :: "n"(n) : "memory")

__device__ __forceinline__ void mma16(float* c, uint32_t a0, uint32_t a1, uint32_t a2,
                                      uint32_t a3, uint32_t b0, uint32_t b1) {
    asm volatile(
        "mma.sync.aligned.m16n8k16.row.col.f32.f16.f16.f32 "
        "{%0,%1,%2,%3},{%4,%5,%6,%7},{%8,%9},{%0,%1,%2,%3};"
        : "+f"(c[0]), "+f"(c[1]), "+f"(c[2]), "+f"(c[3])
        : "r"(a0), "r"(a1), "r"(a2), "r"(a3), "r"(b0), "r"(b1));
}

/* ---------------- prep kernels ---------------- */
__global__ void prep_pack(const float* __restrict__ qkv_w, const float* __restrict__ proj_w) {
    int i = blockIdx.x * 256 + threadIdx.x;
    const float* src;
    __half* dst;
    if (i < 1152 * 384) { src = qkv_w; dst = (__half*)g_wq; }
    else { i -= 1152 * 384; src = proj_w; dst = (__half*)g_wp; }
    int c = i / 384, k = i - c * 384;
    int nb = c >> 7, n = c & 127;
    int kc = k >> 5, k5 = k & 31;
    int gl = k5 >> 4, sl = SLOT((k5 >> 1) & 7);
    size_t hid = ((size_t)((nb * 12 + kc) * 128 + n) * 16 + gl * 8 + sl) * 2 + (k5 & 1);
    dst[hid] = __float2half_rn(src[(size_t)c * 384 + k]);
}

__global__ void prep_bm(const float* __restrict__ mask, const float* __restrict__ table,
                        const int* __restrict__ ridx) {
    const int wv = blockIdx.x, h = blockIdx.y;
    float* dst = g_bm + (size_t)(wv * NH + h) * (NTOK * 56);
    for (int i = threadIdx.x; i < NTOK * NTOK; i += blockDim.x) {
        int r = i / NTOK, c = i - r * NTOK;
        dst[r * 56 + c] = table[ridx[i] * NH + h] + mask[wv * (NTOK * NTOK) + i];
    }
}

/* ---------------- fp16 GEMM, cp.async-pipelined B (identical to R7) ---------------- */
__global__ __launch_bounds__(256, 1)
void gemm_mm(const float* __restrict__ Aext, const float* __restrict__ bias,
             float* __restrict__ Cext, int nbN, int mode) {
    extern __shared__ uint32_t sm[];
    const int tid = threadIdx.x, warp = tid >> 5, lane = tid & 31;
    const int lg = lane >> 2, lt = lane & 3;
    const int warpm = warp & 3, warpn = warp >> 2;
    const int mbase = blockIdx.x * 128;
    const uint32_t* W = mode ? g_wp : g_wq;
    const uint32_t smb = smem_u32(sm);
    const int NC = nbN * 12;
    const uint32_t dBq = ((tid >> 2) * 20 + (tid & 3) * 4) * 4;

    if (mode == 0) {
        for (int i = tid; i < 12288; i += 256) {
            int r = i / 96, c4 = i - r * 96;
            float4 v = *reinterpret_cast<const float4*>(Aext + (size_t)(mbase + r) * 384 + c4 * 4);
            int g = c4 >> 2, p0 = (c4 << 1) & 7;
            sm[r * GA_STRIDE + g * 8 + SLOT(p0)]     = h2u(v.x, v.y);
            sm[r * GA_STRIDE + g * 8 + SLOT(p0 + 1)] = h2u(v.z, v.w);
        }
    } else {
        const float4* s4 = reinterpret_cast<const float4*>(g_ob + (size_t)mbase * 196);
        float4* d4 = reinterpret_cast<float4*>(sm);
        for (int i = tid; i < 6272; i += 256) d4[i] = s4[i];
    }

    #pragma unroll
    for (int p = 0; p < 2; p++) {
        const uint4* s0 = reinterpret_cast<const uint4*>(W + (size_t)p * 2048);
        uint32_t d = smb + (GB_OFF + p * 2560) * 4 + dBq;
        cpa16(d, s0 + tid);
        cpa16(d + 1280 * 4, s0 + 256 + tid);
        CP_COMMIT();
    }

    int rr[4], win[4], tt[4];
    #pragma unroll
    for (int q = 0; q < 4; q++) {
        rr[q] = mbase + warpm * 32 + lg + q * 8;
        win[q] = rr[q] / 49;
        tt[q] = rr[q] - win[q] * 49;
    }

    #pragma unroll 1
    for (int nb = 0; nb < nbN; nb++) {
        float acc[2][8][4];
        #pragma unroll
        for (int a = 0; a < 2; a++)
            #pragma unroll
            for (int f = 0; f < 8; f++)
                #pragma unroll
                for (int c = 0; c < 4; c++) acc[a][f][c] = 0.f;

        #pragma unroll 1
        for (int kc = 0; kc < 12; kc++) {
            const int c = nb * 12 + kc;
            if (c + 2 < NC) {
                const uint4* s0 = reinterpret_cast<const uint4*>(W + (size_t)(c + 2) * 2048);
                uint32_t d = smb + (GB_OFF + ((c + 2) & 3) * 2560) * 4 + dBq;
                cpa16(d, s0 + tid);
                cpa16(d + 1280 * 4, s0 + 256 + tid);
            }
            CP_COMMIT();
            CP_WAIT(2);
            __syncthreads();
            const uint32_t* Bb = sm + GB_OFF + (c & 3) * 2560;
            #pragma unroll
            for (int gl = 0; gl < 2; gl++) {
                const int ab = (kc * 2 + gl) * 8 + 2 * lt;
                const int R = warpm * 32 + lg;
                uint2 lo0 = *reinterpret_cast<const uint2*>(&sm[R * GA_STRIDE + ab]);
                uint2 hi0 = *reinterpret_cast<const uint2*>(&sm[(R + 8) * GA_STRIDE + ab]);
                uint2 lo1 = *reinterpret_cast<const uint2*>(&sm[(R + 16) * GA_STRIDE + ab]);
                uint2 hi1 = *reinterpret_cast<const uint2*>(&sm[(R + 24) * GA_STRIDE + ab]);
                #pragma unroll
                for (int nf = 0; nf < 8; nf++) {
                    int n = warpn * 64 + nf * 8 + lg;
                    uint2 bb = *reinterpret_cast<const uint2*>(&Bb[n * 20 + gl * 8 + 2 * lt]);
                    mma16(acc[0][nf], lo0.x, hi0.x, lo0.y, hi0.y, bb.x, bb.y);
                    mma16(acc[1][nf], lo1.x, hi1.x, lo1.y, hi1.y, bb.x, bb.y);
                }
            }
        }

        if (mode == 1) {
            #pragma unroll
            for (int nf = 0; nf < 8; nf++) {
                int col = nb * 128 + warpn * 64 + nf * 8 + lt * 2;
                float b0 = __ldg(&bias[col]), b1 = __ldg(&bias[col + 1]);
                #pragma unroll
                for (int mt = 0; mt < 2; mt++) {
                    *reinterpret_cast<float2*>(&Cext[(size_t)rr[mt * 2] * 384 + col]) =
                        make_float2(acc[mt][nf][0] + b0, acc[mt][nf][1] + b1);
                    *reinterpret_cast<float2*>(&Cext[(size_t)rr[mt * 2 + 1] * 384 + col]) =
                        make_float2(acc[mt][nf][2] + b0, acc[mt][nf][3] + b1);
                }
            }
        } else {
            const int part = (nb >= 6) ? 2 : ((nb >= 3) ? 1 : 0);
            const int wcb = (nb - part * 3) * 128 + warpn * 64;
            #pragma unroll
            for (int nf = 0; nf < 8; nf++) {
                int wcol = wcb + nf * 8 + lt * 2;
                int h = wcol >> 5, c32 = wcol & 31;
                int gcol = nb * 128 + warpn * 64 + nf * 8 + lt * 2;
                float b0 = __ldg(&bias[gcol]), b1 = __ldg(&bias[gcol + 1]);
                int gA = c32 >> 4, slA = SLOT((c32 >> 1) & 7);
                #pragma unroll
                for (int q = 0; q < 4; q++) {
                    float v0 = acc[q >> 1][nf][(q & 1) * 2 + 0] + b0;
                    float v1 = acc[q >> 1][nf][(q & 1) * 2 + 1] + b1;
                    size_t hd = (size_t)(win[q] * 12 + h);
                    if (part == 0) {
                        g_q[hd * 980 + tt[q] * 20 + gA * 8 + slA] = h2u(v0 * SCALE, v1 * SCALE);
                    } else if (part == 1) {
                        g_k[hd * 980 + tt[q] * 20 + gA * 8 + slA] = h2u(v0, v1);
                    } else {
                        int gt = tt[q] >> 4, slt = SLOT((tt[q] >> 1) & 7);
                        __half* vtb = (__half*)(g_vt + hd * 1152);
                        int u0 = c32 * 36 + gt * 8 + slt;
                        vtb[u0 * 2 + (tt[q] & 1)] = __float2half_rn(v0);
                        vtb[(u0 + 36) * 2 + (tt[q] & 1)] = __float2half_rn(v1);
                    }
                }
            }
        }
    }
}

/* ---------------- attention v2: no smem, no barriers, register-resident P ----------------
   warp = (mt 0..3, hg 0..2); each warp: rows mt*16..+15, full 56 cols, heads hg+3i. */
__global__ __launch_bounds__(384, 2)
void attn_kernel() {
    const int b = blockIdx.x;
    const int wi = b & (NWIN - 1);
    const int tid = threadIdx.x, warp = tid >> 5, lane = tid & 31;
    const int lg = lane >> 2, lt = lane & 3;
    const int mt = warp & 3, hg = warp >> 2;
    const int r0 = mt * 16 + lg, r1 = r0 + 8;
    const bool ok0 = r0 < NTOK, ok1 = r1 < NTOK;

    #pragma unroll 1
    for (int i = 0; i < 4; i++) {
        const int h = hg + 3 * i;
        const size_t hd = (size_t)(b * NH + h);
        const uint32_t* Qp = g_q + hd * 980;
        const uint32_t* Kp = g_k + hd * 980;
        const uint32_t* Vp = g_vt + hd * 1152;
        const float* bmh = g_bm + (size_t)(wi * NH + h) * (NTOK * 56);

        /* Q fragments (direct LDG.64) */
        uint2 q0[2], q1[2];
        #pragma unroll
        for (int g = 0; g < 2; g++) {
            q0[g] = *reinterpret_cast<const uint2*>(Qp + r0 * 20 + g * 8 + 2 * lt);
            q1[g] = *reinterpret_cast<const uint2*>(Qp + r1 * 20 + g * 8 + 2 * lt);
        }

        /* S = q @ k^T : 7 n-tiles x 2 k-steps */
        float sacc[7][4];
        #pragma unroll
        for (int j = 0; j < 7; j++)
            #pragma unroll
            for (int c = 0; c < 4; c++) sacc[j][c] = 0.f;
        #pragma unroll
        for (int g = 0; g < 2; g++)
            #pragma unroll
            for (int j = 0; j < 7; j++) {
                uint2 kb = *reinterpret_cast<const uint2*>(Kp + (j * 8 + lg) * 20 + g * 8 + 2 * lt);
                mma16(sacc[j], q0[g].x, q1[g].x, q0[g].y, q1[g].y, kb.x, kb.y);
            }

        /* + bias/mask, column-validity masking, row max */
        float mx0 = -1e30f, mx1 = -1e30f;
        #pragma unroll
        for (int j = 0; j < 7; j++) {
            int cb = j * 8 + 2 * lt;
            float2 bb0 = ok0 ? *reinterpret_cast<const float2*>(bmh + r0 * 56 + cb)
                             : make_float2(0.f, 0.f);
            float2 bb1 = ok1 ? *reinterpret_cast<const float2*>(bmh + r1 * 56 + cb)
                             : make_float2(0.f, 0.f);
            bool v0 = cb < NTOK, v1 = cb + 1 < NTOK;
            sacc[j][0] = v0 ? sacc[j][0] + bb0.x : -1e30f;
            sacc[j][1] = v1 ? sacc[j][1] + bb0.y : -1e30f;
            sacc[j][2] = v0 ? sacc[j][2] + bb1.x : -1e30f;
            sacc[j][3] = v1 ? sacc[j][3] + bb1.y : -1e30f;
            mx0 = fmaxf(mx0, fmaxf(sacc[j][0], sacc[j][1]));
            mx1 = fmaxf(mx1, fmaxf(sacc[j][2], sacc[j][3]));
        }
        mx0 = fmaxf(mx0, __shfl_xor_sync(0xffffffffu, mx0, 1));
        mx0 = fmaxf(mx0, __shfl_xor_sync(0xffffffffu, mx0, 2));
        mx1 = fmaxf(mx1, __shfl_xor_sync(0xffffffffu, mx1, 1));
        mx1 = fmaxf(mx1, __shfl_xor_sync(0xffffffffu, mx1, 2));

        /* exp + row sum (invalid cols underflow to 0) */
        float sum0 = 0.f, sum1 = 0.f;
        #pragma unroll
        for (int j = 0; j < 7; j++) {
            sacc[j][0] = __expf(sacc[j][0] - mx0);
            sacc[j][1] = __expf(sacc[j][1] - mx0);
            sacc[j][2] = __expf(sacc[j][2] - mx1);
            sacc[j][3] = __expf(sacc[j][3] - mx1);
            sum0 += sacc[j][0] + sacc[j][1];
            sum1 += sacc[j][2] + sacc[j][3];
        }
        sum0 += __shfl_xor_sync(0xffffffffu, sum0, 1);
        sum0 += __shfl_xor_sync(0xffffffffu, sum0, 2);
        sum1 += __shfl_xor_sync(0xffffffffu, sum1, 1);
        sum1 += __shfl_xor_sync(0xffffffffu, sum1, 2);
        float inv0 = 1.f / sum0, inv1 = 1.f / sum1;

        /* pack P directly as A-fragments of the O mma (S C-frag == P A-frag) */
        uint32_t pf[4][4];
        #pragma unroll
        for (int g = 0; g < 3; g++) {
            pf[g][0] = h2u(sacc[2 * g][0] * inv0, sacc[2 * g][1] * inv0);
            pf[g][1] = h2u(sacc[2 * g][2] * inv1, sacc[2 * g][3] * inv1);
            pf[g][2] = h2u(sacc[2 * g + 1][0] * inv0, sacc[2 * g + 1][1] * inv0);
            pf[g][3] = h2u(sacc[2 * g + 1][2] * inv1, sacc[2 * g + 1][3] * inv1);
        }
        pf[3][0] = h2u(sacc[6][0] * inv0, sacc[6][1] * inv0);
        pf[3][1] = h2u(sacc[6][2] * inv1, sacc[6][3] * inv1);
        pf[3][2] = 0u;
        pf[3][3] = 0u;

        /* O = P @ V : 4 n-tiles x 4 k-steps */
        float oacc[4][4];
        #pragma unroll
        for (int nt = 0; nt < 4; nt++)
            #pragma unroll
            for (int c = 0; c < 4; c++) oacc[nt][c] = 0.f;
        #pragma unroll
        for (int g = 0; g < 4; g++)
            #pragma unroll
            for (int nt = 0; nt < 4; nt++) {
                uint2 vb = *reinterpret_cast<const uint2*>(Vp + (nt * 8 + lg) * 36 + g * 8 + 2 * lt);
                mma16(oacc[nt], pf[g][0], pf[g][1], pf[g][2], pf[g][3], vb.x, vb.y);
            }

        /* store O in gemm2's packed A layout */
        #pragma unroll
        for (int nt = 0; nt < 4; nt++) {
            int col = h * 32 + nt * 8 + lt * 2;
            int gA = col >> 4, slA = SLOT((col >> 1) & 7);
            if (ok0)
                g_ob[(size_t)(b * NTOK + r0) * 196 + gA * 8 + slA] = h2u(oacc[nt][0], oacc[nt][1]);
            if (ok1)
                g_ob[(size_t)(b * NTOK + r1) * 196 + gA * 8 + slA] = h2u(oacc[nt][2], oacc[nt][3]);
        }
    }
}

/* ---------------- launcher ---------------- */
extern "C" void kernel_launch(void* const* d_in, const int* in_sizes, int n_in,
                              void* d_out, int out_size) {
    const float* x      = (const float*)d_in[0];
    const float* mask   = (const float*)d_in[1];
    const float* table  = (const float*)d_in[2];
    const float* qkv_w  = (const float*)d_in[3];
    const float* qkv_b  = (const float*)d_in[4];
    const float* proj_w = (const float*)d_in[5];
    const float* proj_b = (const float*)d_in[6];
    const int*   ridx   = (const int*)d_in[7];
    float* out = (float*)d_out;

    cudaFuncSetAttribute(gemm_mm, cudaFuncAttributeMaxDynamicSharedMemorySize, GSMEM_BYTES);

    prep_pack<<<2304, 256>>>(qkv_w, proj_w);
    prep_bm<<<dim3(NWIN, NH), 128>>>(mask, table, ridx);
    gemm_mm<<<NMT, 256, GSMEM_BYTES>>>(x, qkv_b, nullptr, 9, 0);
    attn_kernel<<<NBLK, 384>>>();
    gemm_mm<<<NMT, 256, GSMEM_BYTES>>>(nullptr, proj_b, out, 3, 1);
}